// round 2
// baseline (speedup 1.0000x reference)
#include <cuda_runtime.h>
#include <math.h>

#define NB 8
#define NL 4096
#define NH 8
#define NE 64
#define NM 64
#define NCH 512

typedef unsigned long long u64x;

// ---------------- device scratch (no allocations allowed) ----------------
__device__ float4 g_ts[8192];                         // (cos,cos,sin,sin) of 2*pi*(i&4095)/4096
__device__ float2 g_F[2 * NB * NM * NCH];             // [tensor][b][mode][ch], ch=h*64+e
__device__ float2 g_O[NB * NH * NE * NM];             // [row][mode]: (A_f, B_f) pre-scaled

// ---------------- f32x2 helpers ----------------
static __device__ __forceinline__ u64x fma2(u64x a, u64x b, u64x c) {
    u64x d; asm("fma.rn.f32x2 %0,%1,%2,%3;" : "=l"(d) : "l"(a), "l"(b), "l"(c)); return d;
}
static __device__ __forceinline__ void unpack2(u64x d, float& lo, float& hi) {
    asm("mov.b64 {%0,%1},%2;" : "=f"(lo), "=f"(hi) : "l"(d));
}

// ================= K0: trig table =================
__global__ void k0_init() {
    int i = blockIdx.x * 256 + threadIdx.x;
    if (i < 8192) {
        float s, c;
        sincospif((float)(i & 4095) / 2048.0f, &s, &c);
        g_ts[i] = make_float4(c, c, s, s);
    }
}

// ================= K1: forward sparse DFT =================
// CTA: (ctile 0..7, b 0..7, tensor 0..1), 256 thr. Warp owns 8 modes, lane owns 2 channels.
#define K1_SMEM (8192 * 16 + 64 * 64 * 4)
__global__ void __launch_bounds__(256) k1_forward(const float* __restrict__ qp,
                                                  const float* __restrict__ kp,
                                                  const int* __restrict__ iq,
                                                  const int* __restrict__ ikv) {
    extern __shared__ char sm[];
    float4* ts = (float4*)sm;                 // 8192 * 16B
    const ulonglong2* ts2 = (const ulonglong2*)ts;
    float* xs = (float*)(ts + 8192);          // 64 t x 64 ch
    const u64x* xsd = (const u64x*)xs;

    const int ctile = blockIdx.x, b = blockIdx.y;
    const float* src = blockIdx.z ? kp : qp;
    const int* idxarr = blockIdx.z ? ikv : iq;
    const int tid = threadIdx.x, lane = tid & 31, warp = tid >> 5;

    for (int i = tid; i < 8192; i += 256) ts[i] = g_ts[i];

    int F[8];
    u64x accR[8], accI[8];
#pragma unroll
    for (int i = 0; i < 8; i++) { F[i] = idxarr[warp * 8 + i]; accR[i] = 0ull; accI[i] = 0ull; }

    const float* base = src + (size_t)b * NL * NCH + ctile * 64;

    for (int chunk = 0; chunk < 64; chunk++) {
        __syncthreads();
        for (int i = tid; i < 1024; i += 256) {          // stage 64t x 64ch as float4
            int tt = i >> 4, c4 = i & 15;
            ((float4*)xs)[i] = *(const float4*)(base + (size_t)(chunk * 64 + tt) * NCH + c4 * 4);
        }
        __syncthreads();
        int idx[8];
#pragma unroll
        for (int i = 0; i < 8; i++) idx[i] = (F[i] * (chunk * 64)) & 4095;
        for (int tt = 0; tt < 64; tt++) {
            u64x x = xsd[tt * 32 + lane];
#pragma unroll
            for (int i = 0; i < 8; i++) {
                ulonglong2 cs = ts2[idx[i]];     // (cc, ss) broadcast
                accR[i] = fma2(x, cs.x, accR[i]);
                accI[i] = fma2(x, cs.y, accI[i]);
                idx[i] += F[i];                  // stays < 8192 within a chunk (F < 64)
            }
        }
    }

    const int ch = ctile * 64 + lane * 2;
    float2* dst = g_F + ((size_t)(blockIdx.z * NB + b) * NM) * NCH;
#pragma unroll
    for (int i = 0; i < 8; i++) {
        int f = warp * 8 + i;
        float r0, r1, s0, s1;
        unpack2(accR[i], r0, r1);
        unpack2(accI[i], s0, s1);
        dst[(size_t)f * NCH + ch]     = make_float2(r0, -s0);
        dst[(size_t)f * NCH + ch + 1] = make_float2(r1, -s1);
    }
}

// ================= K2: per-(b,h) complex middle =================
#define K2_SMEM (5 * 4096 * 8)
__global__ void __launch_bounds__(256) k2_middle(const float* __restrict__ w1,
                                                 const float* __restrict__ w2) {
    extern __shared__ char sm[];
    float2* sFq  = (float2*)sm;        // [x][e]
    float2* sFkT = sFq + 4096;         // [e][y]
    float2* sFkY = sFkT + 4096;        // [y][e]
    float2* sA   = sFkY + 4096;        // [y][x]
    float2* sC   = sA + 4096;          // [e][x]

    const int bh = blockIdx.x, b = bh >> 3, h = bh & 7;
    const int tid = threadIdx.x;

    for (int i = tid; i < 4096; i += 256) {
        int e = i & 63, f = i >> 6;
        float2 vq = g_F[((size_t)(b) * NM + f) * NCH + h * 64 + e];
        float2 vk = g_F[((size_t)(NB + b) * NM + f) * NCH + h * 64 + e];
        sFq[f * 64 + e]  = vq;
        sFkT[e * 64 + f] = vk;
        sFkY[f * 64 + e] = vk;
    }
    __syncthreads();

    // A[x][y] = tanh_c( sum_e Fq[e,x] * Fk[e,y] )   (no conjugate)
#pragma unroll 1
    for (int p = 0; p < 16; p++) {
        int i = p * 256 + tid, x = i >> 6, y = i & 63;
        float re = 0.f, im = 0.f;
#pragma unroll 4
        for (int e = 0; e < 64; e++) {
            float2 a = sFq[x * 64 + e];    // broadcast (x fixed per warp)
            float2 c = sFkT[e * 64 + y];   // lanes consecutive
            re += a.x * c.x - a.y * c.y;
            im += a.x * c.y + a.y * c.x;
        }
        sA[y * 64 + x] = make_float2(tanhf(re), tanhf(im));
    }
    __syncthreads();

    // C[e][x] = sum_y A[x,y] * Fk[e,y]
#pragma unroll 1
    for (int p = 0; p < 16; p++) {
        int i = p * 256 + tid, x = i & 63, e = i >> 6;
        float re = 0.f, im = 0.f;
#pragma unroll 4
        for (int y = 0; y < 64; y++) {
            float2 a = sA[y * 64 + x];     // lanes consecutive
            float2 kv = sFkY[y * 64 + e];  // broadcast (e fixed per warp)
            re += a.x * kv.x - a.y * kv.y;
            im += a.x * kv.y + a.y * kv.x;
        }
        sC[e * 64 + x] = make_float2(re, im);
    }
    __syncthreads();

    // O[o][x] = sum_e C[e,x] * (w1 + i w2)[h,e,o,x]; pre-scale for irfft
#pragma unroll 1
    for (int p = 0; p < 16; p++) {
        int i = p * 256 + tid, x = i & 63, o = i >> 6;
        float re = 0.f, im = 0.f;
        size_t wbase = (((size_t)h * 64) * 64 + o) * 64 + x;
#pragma unroll 4
        for (int e = 0; e < 64; e++) {
            float2 c = sC[e * 64 + x];
            float wr = w1[wbase + (size_t)e * 4096];
            float wi = w2[wbase + (size_t)e * 4096];
            re += c.x * wr - c.y * wi;
            im += c.x * wi + c.y * wr;
        }
        float s = (x == 0 ? 1.0f : 2.0f) * 9.313225746154785e-10f;  // 2^-30 (or 2^-29)
        int row = (b * 8 + h) * 64 + o;
        g_O[(size_t)row * NM + x] = make_float2(s * re, -s * im);
    }
}

// ================= K3: inverse sparse DFT =================
// out[row][t] = sum_f A_f cos(2pi F_f t/4096) + B_f sin(...)
#define K3_SMEM (8192 * 16 + 16384 + 16384 + 64 * 65 * 4 + 256)
__global__ void __launch_bounds__(256) k3_inverse(float* __restrict__ out,
                                                  const int* __restrict__ iq) {
    extern __shared__ char sm[];
    float4* ts = (float4*)sm;                      // 8192 * 16B
    const ulonglong2* ts2 = (const ulonglong2*)ts;
    float* sA = (float*)(ts + 8192);               // [f][row]  64x64
    float* sB = sA + 4096;                         // [f][row]
    float* strans = sB + 4096;                     // [row][65]
    int* sF = (int*)(strans + 64 * 65);            // [64]

    const int rt = blockIdx.x, th = blockIdx.y;
    const int r0 = rt * 64;
    const int tid = threadIdx.x, lane = tid & 31, warp = tid >> 5;

    for (int i = tid; i < 8192; i += 256) ts[i] = g_ts[i];
    for (int i = tid; i < 4096; i += 256) {
        int f = i & 63, rr = i >> 6;
        float2 v = g_O[(size_t)(r0 + rr) * NM + f];
        sA[f * 64 + rr] = v.x;
        sB[f * 64 + rr] = v.y;
    }
    if (tid < 64) sF[tid] = iq[tid];
    __syncthreads();

    const u64x* sAd = (const u64x*)sA;
    const u64x* sBd = (const u64x*)sB;

#pragma unroll 1
    for (int pass = 0; pass < 32; pass++) {
        const int tbase = th * 2048 + pass * 64;
        const int t0 = tbase + warp * 8;
        u64x acc[8];
#pragma unroll
        for (int j = 0; j < 8; j++) acc[j] = 0ull;

#pragma unroll 1
        for (int f = 0; f < 64; f++) {
            int Ff = sF[f];
            u64x aa = sAd[f * 32 + lane];
            u64x bb = sBd[f * 32 + lane];
            int id = (Ff * t0) & 4095;            // id + 7*Ff < 8192 (Ff < 64)
#pragma unroll
            for (int j = 0; j < 8; j++) {
                ulonglong2 cs = ts2[id];
                acc[j] = fma2(aa, cs.x, acc[j]);
                acc[j] = fma2(bb, cs.y, acc[j]);
                id += Ff;
            }
        }

        __syncthreads();   // prior pass's strans readers done
#pragma unroll
        for (int j = 0; j < 8; j++) {
            float v0, v1;
            unpack2(acc[j], v0, v1);
            int tl = warp * 8 + j;
            strans[(2 * lane) * 65 + tl]     = v0;
            strans[(2 * lane + 1) * 65 + tl] = v1;
        }
        __syncthreads();
        for (int i = tid; i < 1024; i += 256) {
            int rr = i >> 4, c4 = i & 15;
            const float* sp = strans + rr * 65 + c4 * 4;
            float4 vv = make_float4(sp[0], sp[1], sp[2], sp[3]);
            *(float4*)&out[(size_t)(r0 + rr) * NL + tbase + c4 * 4] = vv;
        }
    }
}

// ================= launch =================
extern "C" void kernel_launch(void* const* d_in, const int* in_sizes, int n_in,
                              void* d_out, int out_size) {
    const float* q  = (const float*)d_in[0];
    const float* k  = (const float*)d_in[1];
    // d_in[2] = v, never used by the reference
    const float* w1 = (const float*)d_in[3];
    const float* w2 = (const float*)d_in[4];
    const int* iq   = (const int*)d_in[5];
    const int* ikv  = (const int*)d_in[6];
    float* out = (float*)d_out;

    cudaFuncSetAttribute(k1_forward, cudaFuncAttributeMaxDynamicSharedMemorySize, K1_SMEM);
    cudaFuncSetAttribute(k2_middle,  cudaFuncAttributeMaxDynamicSharedMemorySize, K2_SMEM);
    cudaFuncSetAttribute(k3_inverse, cudaFuncAttributeMaxDynamicSharedMemorySize, K3_SMEM);

    k0_init<<<32, 256>>>();
    k1_forward<<<dim3(8, NB, 2), 256, K1_SMEM>>>(q, k, iq, ikv);
    k2_middle<<<NB * NH, 256, K2_SMEM>>>(w1, w2);
    k3_inverse<<<dim3(64, 2), 256, K3_SMEM>>>(out, iq);
}

// round 3
// speedup vs baseline: 2.4507x; 2.4507x over previous
#include <cuda_runtime.h>
#include <math.h>

#define NB 8
#define NL 4096
#define NH 8
#define NM 64
#define NCH 512

typedef unsigned long long u64x;

// ---------------- device scratch ----------------
__device__ ulonglong2 g_ts[4096];            // (cc, ss) packed f32x2 of angle 2*pi*i/4096
__device__ float2 g_F[2 * NB * NM * NCH];    // [tensor][b][mode-pos][ch]
__device__ float2 g_O[NB * NH * 64 * NM];    // [row][mode-pos]: (A, B) pre-scaled

// ---------------- f32x2 helpers ----------------
static __device__ __forceinline__ u64x fma2(u64x a, u64x b, u64x c) {
    u64x d; asm("fma.rn.f32x2 %0,%1,%2,%3;" : "=l"(d) : "l"(a), "l"(b), "l"(c)); return d;
}
static __device__ __forceinline__ u64x add2(u64x a, u64x b) {
    u64x d; asm("add.rn.f32x2 %0,%1,%2;" : "=l"(d) : "l"(a), "l"(b)); return d;
}
#define NEG1X2 0xBF800000BF800000ULL
static __device__ __forceinline__ u64x sub2(u64x a, u64x b) { return fma2(b, NEG1X2, a); }
static __device__ __forceinline__ u64x neg2(u64x a) { return fma2(a, NEG1X2, 0ULL); }
static __device__ __forceinline__ void unpack2(u64x d, float& lo, float& hi) {
    asm("mov.b64 {%0,%1},%2;" : "=f"(lo), "=f"(hi) : "l"(d));
}

// ================= K0: trig table =================
__global__ void k0_init() {
    int i = blockIdx.x * 256 + threadIdx.x;
    if (i < 4096) {
        float s, c;
        sincospif((float)i / 2048.0f, &s, &c);
        u64x cc, ss;
        asm("mov.b64 %0,{%1,%1};" : "=l"(cc) : "f"(c));
        asm("mov.b64 %0,{%1,%1};" : "=l"(ss) : "f"(s));
        g_ts[i] = make_ulonglong2(cc, ss);
    }
}

// ================= K1: forward sparse DFT (radix-4) =================
// X[f] = sum_{t'=0}^{1023} u_{f&3}(t') e^{-i 2pi f t'/4096}
// u0=a+c, u2=a-c (real); u1=bq-i*d, u3=bq+i*d;  a=x0+x2, bq=x0-x2, c=x1+x3, d=x1-x3
// Conventions: accR=Re, accS accumulates so that Im = -accS for all classes.
template<int CLS>
static __device__ __forceinline__ void k1_chunk(
    const u64x* __restrict__ xsd, const ulonglong2* __restrict__ ts2,
    int lane, u64x accR[4], u64x accS[4], int idx[4], const int F[4])
{
#pragma unroll 2
    for (int tt = 0; tt < 32; tt++) {
        u64x x0 = xsd[(0 * 32 + tt) * 32 + lane];
        u64x x1 = xsd[(1 * 32 + tt) * 32 + lane];
        u64x x2 = xsd[(2 * 32 + tt) * 32 + lane];
        u64x x3 = xsd[(3 * 32 + tt) * 32 + lane];
        u64x P, QR = 0, QS = 0;
        if (CLS == 0) {
            P = add2(add2(x0, x2), add2(x1, x3));
        } else if (CLS == 2) {
            P = sub2(add2(x0, x2), add2(x1, x3));
        } else {
            u64x bq = sub2(x0, x2);
            u64x d  = sub2(x1, x3);
            u64x nd = neg2(d);
            P  = bq;
            QR = (CLS == 1) ? nd : d;   // accR += P*cc + QR*ss
            QS = (CLS == 1) ? d  : nd;  // accS += P*ss + QS*cc
        }
#pragma unroll
        for (int k = 0; k < 4; k++) {
            ulonglong2 cs = ts2[idx[k]];
            accR[k] = fma2(P, cs.x, accR[k]);
            accS[k] = fma2(P, cs.y, accS[k]);
            if (CLS & 1) {
                accR[k] = fma2(QR, cs.y, accR[k]);
                accS[k] = fma2(QS, cs.x, accS[k]);
            }
            idx[k] = (idx[k] + F[k]) & 4095;
        }
    }
}

// generic (mixed-class) fallback: plain non-decimated accumulation
static __device__ __forceinline__ void k1_chunk_gen(
    const u64x* __restrict__ xsd, const ulonglong2* __restrict__ ts2,
    int lane, u64x accR[4], u64x accS[4], int chunk, const int F[4])
{
    for (int tt = 0; tt < 32; tt++) {
        int tp = chunk * 32 + tt;
#pragma unroll
        for (int m = 0; m < 4; m++) {
            u64x x = xsd[(m * 32 + tt) * 32 + lane];
            int tg = tp + 1024 * m;
#pragma unroll
            for (int k = 0; k < 4; k++) {
                int id = (F[k] * tg) & 4095;
                ulonglong2 cs = ts2[id];
                accR[k] = fma2(x, cs.x, accR[k]);
                accS[k] = fma2(x, cs.y, accS[k]);
            }
        }
    }
}

#define K1_SMEM (4096 * 16 + 4 * 32 * 64 * 4)   // 64KB trig + 32KB stage = 98304
__global__ void __launch_bounds__(256, 2) k1_forward(const float* __restrict__ qp,
                                                     const float* __restrict__ kp,
                                                     const int* __restrict__ iq,
                                                     const int* __restrict__ ikv) {
    extern __shared__ char sm[];
    ulonglong2* ts2 = (ulonglong2*)sm;
    float* xs = (float*)(ts2 + 4096);            // [4 m][32 t'][64 ch]
    const u64x* xsd = (const u64x*)xs;

    const int ctile = blockIdx.x, b = blockIdx.y;
    const int tensor = blockIdx.z >> 1, mhalf = blockIdx.z & 1;
    const float* src = tensor ? kp : qp;
    const int* idxarr = tensor ? ikv : iq;
    const int tid = threadIdx.x, lane = tid & 31, warp = tid >> 5;

    for (int i = tid; i < 4096; i += 256) ts2[i] = g_ts[i];

    // --- per-warp mode resolution: bucket modes by (F&3), warp gw takes bucketed [4gw,4gw+4) ---
    const unsigned FULL = 0xffffffffu;
    int gw = mhalf * 8 + warp;
    int Flo = idxarr[lane], Fhi = idxarr[lane + 32];
    int clo = Flo & 3, chi = Fhi & 3;
    unsigned mlo[4], mhi[4];
    int off[5]; off[0] = 0;
#pragma unroll
    for (int c = 0; c < 4; c++) {
        mlo[c] = __ballot_sync(FULL, clo == c);
        mhi[c] = __ballot_sync(FULL, chi == c);
    }
#pragma unroll
    for (int c = 0; c < 4; c++) off[c + 1] = off[c] + __popc(mlo[c]) + __popc(mhi[c]);
    unsigned lm = (1u << lane) - 1u;
    int p_lo = off[clo] + __popc(mlo[clo] & lm);
    int p_hi = off[chi] + __popc(mlo[chi]) + __popc(mhi[chi] & lm);
    int mi[4], F[4];
#pragma unroll
    for (int k = 0; k < 4; k++) {
        int tpos = gw * 4 + k;
        unsigned ba = __ballot_sync(FULL, p_lo == tpos);
        unsigned bb = __ballot_sync(FULL, p_hi == tpos);
        int m = ba ? (__ffs(ba) - 1) : (32 + __ffs(bb) - 1);
        mi[k] = m;
        F[k] = __shfl_sync(FULL, (m < 32) ? Flo : Fhi, m & 31);
    }
    int jcls = F[0] & 3;
    bool uni = ((F[1] & 3) == jcls) && ((F[2] & 3) == jcls) && ((F[3] & 3) == jcls);

    u64x accR[4], accS[4]; int idx[4];
#pragma unroll
    for (int k = 0; k < 4; k++) { accR[k] = 0; accS[k] = 0; idx[k] = 0; }

    const float* base = src + (size_t)b * NL * NCH + ctile * 64;

    for (int chunk = 0; chunk < 32; chunk++) {
        __syncthreads();
#pragma unroll
        for (int ii = 0; ii < 8; ii++) {
            int i = ii * 256 + tid;                 // 2048 float4
            int c4 = i & 15, tt = (i >> 4) & 31, m = i >> 9;
            ((float4*)xs)[i] = *(const float4*)(base + (size_t)(chunk * 32 + tt + 1024 * m) * NCH + c4 * 4);
        }
        __syncthreads();
        if (uni) {
            switch (jcls) {
                case 0: k1_chunk<0>(xsd, ts2, lane, accR, accS, idx, F); break;
                case 1: k1_chunk<1>(xsd, ts2, lane, accR, accS, idx, F); break;
                case 2: k1_chunk<2>(xsd, ts2, lane, accR, accS, idx, F); break;
                default: k1_chunk<3>(xsd, ts2, lane, accR, accS, idx, F); break;
            }
        } else {
            k1_chunk_gen(xsd, ts2, lane, accR, accS, chunk, F);
        }
    }

    const int ch = ctile * 64 + lane * 2;
    float2* dst = g_F + ((size_t)(tensor * NB + b) * NM) * NCH;
#pragma unroll
    for (int k = 0; k < 4; k++) {
        float r0, r1, s0, s1;
        unpack2(accR[k], r0, r1);
        unpack2(accS[k], s0, s1);
        dst[(size_t)mi[k] * NCH + ch]     = make_float2(r0, -s0);
        dst[(size_t)mi[k] * NCH + ch + 1] = make_float2(r1, -s1);
    }
}

// ================= K2: per-(b,h) complex middle, x-split =================
#define K2_SMEM ((64*64 + 64*65 + 64*64 + 64*65 + 64*64) * 8)
__global__ void __launch_bounds__(256, 1) k2_middle(const float* __restrict__ w1,
                                                    const float* __restrict__ w2,
                                                    const int* __restrict__ iq) {
    extern __shared__ char sm[];
    float2* sFq  = (float2*)sm;          // [x][e]   64*64
    float2* sFkT = sFq + 64 * 64;        // [e][y]   64*65 (pad)
    float2* sFkY = sFkT + 64 * 65;       // [y][e]   64*64
    float2* sA   = sFkY + 64 * 64;       // [y][x]   64*65 (pad)
    float2* sC   = sA + 64 * 65;         // [e][x]   64*64

    const int bh = blockIdx.x, b = bh >> 3, h = bh & 7;
    const int xh = blockIdx.y;           // x-half
    const int tid = threadIdx.x;

    for (int i = tid; i < 4096; i += 256) {
        int e = i & 63, f = i >> 6;
        float2 vq = g_F[((size_t)(b) * NM + f) * NCH + h * 64 + e];
        float2 vk = g_F[((size_t)(NB + b) * NM + f) * NCH + h * 64 + e];
        sFq[f * 64 + e]  = vq;
        sFkT[e * 65 + f] = vk;
        sFkY[f * 64 + e] = vk;
    }
    __syncthreads();

    // A[x][y] = tanh_c( sum_e Fq[e,x] * Fk[e,y] )
#pragma unroll 1
    for (int p = 0; p < 8; p++) {
        int i = p * 256 + tid, x = xh * 32 + (i >> 6), y = i & 63;
        float re = 0.f, im = 0.f;
#pragma unroll 4
        for (int e = 0; e < 64; e++) {
            float2 a = sFq[x * 64 + e];     // broadcast
            float2 c = sFkT[e * 65 + y];    // consecutive
            re += a.x * c.x - a.y * c.y;
            im += a.x * c.y + a.y * c.x;
        }
        sA[y * 65 + x] = make_float2(tanhf(re), tanhf(im));
    }
    __syncthreads();

    // C[e][x] = sum_y A[x,y] * Fk[e,y]
#pragma unroll 1
    for (int p = 0; p < 8; p++) {
        int i = p * 256 + tid, x = xh * 32 + (i & 31), e = i >> 5;
        float re = 0.f, im = 0.f;
#pragma unroll 4
        for (int y = 0; y < 64; y++) {
            float2 a  = sA[y * 65 + x];     // consecutive
            float2 kv = sFkY[y * 64 + e];   // broadcast
            re += a.x * kv.x - a.y * kv.y;
            im += a.x * kv.y + a.y * kv.x;
        }
        sC[e * 64 + x] = make_float2(re, im);
    }
    __syncthreads();

    // O[o][x] = sum_e C[e,x] * (w1 + i w2)[h,e,o,x]; pre-scale for irfft
#pragma unroll 1
    for (int p = 0; p < 8; p++) {
        int i = p * 256 + tid, x = xh * 32 + (i & 31), o = i >> 5;
        float re = 0.f, im = 0.f;
        size_t wbase = (((size_t)h * 64) * 64 + o) * 64 + x;
#pragma unroll 4
        for (int e = 0; e < 64; e++) {
            float2 c = sC[e * 64 + x];
            float wr = w1[wbase + (size_t)e * 4096];
            float wi = w2[wbase + (size_t)e * 4096];
            re += c.x * wr - c.y * wi;
            im += c.x * wi + c.y * wr;
        }
        int fx = iq[x];
        float s = ((fx == 0) || (fx == NL / 2) ? 1.0f : 2.0f) * 9.313225746154785e-10f; // 2^-30
        int row = (b * 8 + h) * 64 + o;
        g_O[(size_t)row * NM + x] = make_float2(s * re, -s * im);
    }
}

// ================= K3: inverse sparse DFT (radix-4 reconstruction) =================
// out[t'+1024m] = sum_f P_f cos(pi/2 j m) + Q_f sin(pi/2 j m), j=F&3
// P = A cc + B ss ; Q = B cc - A ss   (per t')
#define K3_SMEM (4096*16 + 4096*4*2 + 64*33*4 + 64*8 + 32)
__global__ void __launch_bounds__(256, 2) k3_inverse(float* __restrict__ out,
                                                     const int* __restrict__ iq) {
    extern __shared__ char sm[];
    ulonglong2* ts2 = (ulonglong2*)sm;            // 64KB
    float* sA = (float*)(ts2 + 4096);             // [pos][64 rows]
    float* sB = sA + 4096;
    float* sT = sB + 4096;                        // [64 rows][33]
    int2* sperm = (int2*)(sT + 64 * 33);          // bucketed pos -> (orig pos, freq)
    int* soff = (int*)(sperm + 64);               // class offsets [5]

    const int rt = blockIdx.x;                    // 64 row tiles
    const int tq = blockIdx.y;                    // 4 t' quarters
    const int r0 = rt * 64;
    const int tid = threadIdx.x, lane = tid & 31, warp = tid >> 5;

    for (int i = tid; i < 4096; i += 256) ts2[i] = g_ts[i];
    for (int i = tid; i < 4096; i += 256) {
        int f = i >> 6, rr = i & 63;
        float2 v = g_O[(size_t)(r0 + rr) * NM + f];
        sA[f * 64 + rr] = v.x;
        sB[f * 64 + rr] = v.y;
    }
    if (warp == 0) {
        const unsigned FULL = 0xffffffffu;
        int Flo = iq[lane], Fhi = iq[lane + 32];
        int clo = Flo & 3, chi = Fhi & 3;
        unsigned mlo[4], mhi[4];
        int off[5]; off[0] = 0;
#pragma unroll
        for (int c = 0; c < 4; c++) {
            mlo[c] = __ballot_sync(FULL, clo == c);
            mhi[c] = __ballot_sync(FULL, chi == c);
        }
#pragma unroll
        for (int c = 0; c < 4; c++) off[c + 1] = off[c] + __popc(mlo[c]) + __popc(mhi[c]);
        unsigned lmm = (1u << lane) - 1u;
        int p_lo = off[clo] + __popc(mlo[clo] & lmm);
        int p_hi = off[chi] + __popc(mlo[chi]) + __popc(mhi[chi] & lmm);
        sperm[p_lo] = make_int2(lane, Flo);
        sperm[p_hi] = make_int2(lane + 32, Fhi);
        if (lane < 5) soff[lane] = off[lane];
    }
    __syncthreads();

    const u64x* sAd = (const u64x*)sA;
    const u64x* sBd = (const u64x*)sB;
    const int o0 = soff[0], o1 = soff[1], o2 = soff[2], o3 = soff[3], o4 = soff[4];

#pragma unroll 1
    for (int pass = 0; pass < 8; pass++) {
        const int t0 = tq * 256 + pass * 32 + warp * 4;
        u64x S[4][4];
        u64x P[4], Q[4];
#pragma unroll
        for (int j = 0; j < 4; j++) P[j] = 0;

        // class 0: S_m += P
#pragma unroll 2
        for (int pos = o0; pos < o1; pos++) {
            int2 pf = sperm[pos];
            u64x A = sAd[pf.x * 32 + lane], B = sBd[pf.x * 32 + lane];
            int id = (pf.y * t0) & 4095;
#pragma unroll
            for (int j = 0; j < 4; j++) {
                ulonglong2 cs = ts2[id];
                P[j] = fma2(A, cs.x, P[j]);
                P[j] = fma2(B, cs.y, P[j]);
                id = (id + pf.y) & 4095;
            }
        }
#pragma unroll
        for (int j = 0; j < 4; j++) { S[0][j] = P[j]; S[1][j] = P[j]; S[2][j] = P[j]; S[3][j] = P[j]; }

        // class 1: S0+=P, S1+=Q, S2-=P, S3-=Q
#pragma unroll
        for (int j = 0; j < 4; j++) { P[j] = 0; Q[j] = 0; }
#pragma unroll 2
        for (int pos = o1; pos < o2; pos++) {
            int2 pf = sperm[pos];
            u64x A = sAd[pf.x * 32 + lane], B = sBd[pf.x * 32 + lane];
            u64x nA = neg2(A);
            int id = (pf.y * t0) & 4095;
#pragma unroll
            for (int j = 0; j < 4; j++) {
                ulonglong2 cs = ts2[id];
                P[j] = fma2(A, cs.x, P[j]);  P[j] = fma2(B, cs.y, P[j]);
                Q[j] = fma2(B, cs.x, Q[j]);  Q[j] = fma2(nA, cs.y, Q[j]);
                id = (id + pf.y) & 4095;
            }
        }
#pragma unroll
        for (int j = 0; j < 4; j++) {
            S[0][j] = add2(S[0][j], P[j]);  S[1][j] = add2(S[1][j], Q[j]);
            S[2][j] = sub2(S[2][j], P[j]);  S[3][j] = sub2(S[3][j], Q[j]);
        }

        // class 2: S0+=P, S1-=P, S2+=P, S3-=P
#pragma unroll
        for (int j = 0; j < 4; j++) P[j] = 0;
#pragma unroll 2
        for (int pos = o2; pos < o3; pos++) {
            int2 pf = sperm[pos];
            u64x A = sAd[pf.x * 32 + lane], B = sBd[pf.x * 32 + lane];
            int id = (pf.y * t0) & 4095;
#pragma unroll
            for (int j = 0; j < 4; j++) {
                ulonglong2 cs = ts2[id];
                P[j] = fma2(A, cs.x, P[j]);
                P[j] = fma2(B, cs.y, P[j]);
                id = (id + pf.y) & 4095;
            }
        }
#pragma unroll
        for (int j = 0; j < 4; j++) {
            S[0][j] = add2(S[0][j], P[j]);  S[1][j] = sub2(S[1][j], P[j]);
            S[2][j] = add2(S[2][j], P[j]);  S[3][j] = sub2(S[3][j], P[j]);
        }

        // class 3: S0+=P, S1-=Q, S2-=P, S3+=Q
#pragma unroll
        for (int j = 0; j < 4; j++) { P[j] = 0; Q[j] = 0; }
#pragma unroll 2
        for (int pos = o3; pos < o4; pos++) {
            int2 pf = sperm[pos];
            u64x A = sAd[pf.x * 32 + lane], B = sBd[pf.x * 32 + lane];
            u64x nA = neg2(A);
            int id = (pf.y * t0) & 4095;
#pragma unroll
            for (int j = 0; j < 4; j++) {
                ulonglong2 cs = ts2[id];
                P[j] = fma2(A, cs.x, P[j]);  P[j] = fma2(B, cs.y, P[j]);
                Q[j] = fma2(B, cs.x, Q[j]);  Q[j] = fma2(nA, cs.y, Q[j]);
                id = (id + pf.y) & 4095;
            }
        }
#pragma unroll
        for (int j = 0; j < 4; j++) {
            S[0][j] = add2(S[0][j], P[j]);  S[1][j] = sub2(S[1][j], Q[j]);
            S[2][j] = sub2(S[2][j], P[j]);  S[3][j] = add2(S[3][j], Q[j]);
        }

        // store 4 quadrants via smem transpose
#pragma unroll
        for (int m = 0; m < 4; m++) {
            __syncthreads();
#pragma unroll
            for (int j = 0; j < 4; j++) {
                float v0, v1;
                unpack2(S[m][j], v0, v1);
                int tl = warp * 4 + j;
                sT[(2 * lane) * 33 + tl]     = v0;
                sT[(2 * lane + 1) * 33 + tl] = v1;
            }
            __syncthreads();
            int tbase = m * 1024 + tq * 256 + pass * 32;
#pragma unroll
            for (int ii = 0; ii < 2; ii++) {
                int i = ii * 256 + tid;        // 512 float4
                int rr = i >> 3, c4 = i & 7;
                const float* sp = sT + rr * 33 + c4 * 4;
                float4 vv = make_float4(sp[0], sp[1], sp[2], sp[3]);
                *(float4*)&out[(size_t)(r0 + rr) * NL + tbase + c4 * 4] = vv;
            }
        }
    }
}

// ================= launch =================
extern "C" void kernel_launch(void* const* d_in, const int* in_sizes, int n_in,
                              void* d_out, int out_size) {
    const float* q  = (const float*)d_in[0];
    const float* k  = (const float*)d_in[1];
    // d_in[2] = v, never used by the reference
    const float* w1 = (const float*)d_in[3];
    const float* w2 = (const float*)d_in[4];
    const int* iq   = (const int*)d_in[5];
    const int* ikv  = (const int*)d_in[6];
    float* out = (float*)d_out;

    cudaFuncSetAttribute(k1_forward, cudaFuncAttributeMaxDynamicSharedMemorySize, K1_SMEM);
    cudaFuncSetAttribute(k2_middle,  cudaFuncAttributeMaxDynamicSharedMemorySize, K2_SMEM);
    cudaFuncSetAttribute(k3_inverse, cudaFuncAttributeMaxDynamicSharedMemorySize, K3_SMEM);

    k0_init<<<16, 256>>>();
    k1_forward<<<dim3(8, NB, 4), 256, K1_SMEM>>>(q, k, iq, ikv);
    k2_middle<<<dim3(NB * NH, 2), 256, K2_SMEM>>>(w1, w2, iq);
    k3_inverse<<<dim3(64, 4), 256, K3_SMEM>>>(out, iq);
}